// round 11
// baseline (speedup 1.0000x reference)
#include <cuda_runtime.h>
#include <cuda_bf16.h>

#define BATCH 8
#define SEQ   8192
#define DMODEL 1024
#define NTOK (BATCH * SEQ)
#define FULL 0xFFFFFFFFu

// Scratch: sortable keys per token. Active key = monotone uint transform of
// score (always >= 0x00800000); inactive = 0.
__device__ unsigned int g_keys[NTOK];
// Per-row 2048-bin pass-1 histogram (top 11 key bits), built by score_kernel,
// consumed AND reset by select_kernel each launch (zero-init at load).
__device__ int g_hist[BATCH * 2048];

// ---------------------------------------------------------------------------
// Kernel 1: scores + keys + pass-1 histogram (hidden under the HBM stream).
// ---------------------------------------------------------------------------
__global__ void __launch_bounds__(256)
score_kernel(const float* __restrict__ hidden,
             const unsigned int* __restrict__ mask,
             const float* __restrict__ w,
             const float* __restrict__ bias)
{
    int warp = (blockIdx.x * blockDim.x + threadIdx.x) >> 5;
    int lane = threadIdx.x & 31;
    if (warp >= NTOK) return;

    const float4* hp = reinterpret_cast<const float4*>(hidden + (size_t)warp * DMODEL);
    const float4* wp = reinterpret_cast<const float4*>(w);

    float acc = 0.0f;
#pragma unroll
    for (int i = 0; i < 8; i++) {
        float4 a = __ldcs(hp + lane + i * 32);   // streaming, evict-first
        float4 c = wp[lane + i * 32];            // hot in L1
        acc += a.x * c.x + a.y * c.y + a.z * c.z + a.w * c.w;
    }
#pragma unroll
    for (int o = 16; o; o >>= 1) acc += __shfl_xor_sync(FULL, acc, o);

    if (lane == 0) {
        float s = acc + bias[0];
        unsigned int u = __float_as_uint(s);
        u = (u & 0x80000000u) ? ~u : (u | 0x80000000u);      // order-preserving
        unsigned int key = (mask[warp] != 0u) ? u : 0u;      // inactive -> 0
        g_keys[warp] = key;
        // pass-1 histogram: REDG spread over 16K addresses, hidden by stream
        atomicAdd(&g_hist[(warp >> 13) * 2048 + (key >> 21)], 1);
    }
}

// ---------------------------------------------------------------------------
// Kernel 2: per-row exact variable top-k, stable lowest-index tie break.
// Pass 1 arrives prebuilt; only passes [20:10] (2048 bins) and [9:0]
// (1024 bins) run here. mneed falls out of the radix-select invariant.
// ---------------------------------------------------------------------------

// In-place suffix scan of hist[0..NB) (hist[NB] must be 0). After this,
// hist[b] = sum_{j>=b} count[j]. Ends with __syncthreads.
template<int NB, int BPT>
__device__ __forceinline__ void suffix_scan(int* hist, int* wsum)
{
    const int tid = threadIdx.x, lane = tid & 31, wid = tid >> 5;
    const bool own = (tid * BPT) < NB;
    const int base = NB - 1 - tid * BPT;

    int local = 0;
    if (own) {
#pragma unroll
        for (int i = 0; i < BPT; i++) local += hist[base - i];
    }
    int s = local;
#pragma unroll
    for (int d = 1; d < 32; d <<= 1) {
        int n2 = __shfl_up_sync(FULL, s, d);
        if (lane >= d) s += n2;
    }
    if (lane == 31) wsum[wid] = s;
    __syncthreads();
    if (wid == 0) {
        int x = wsum[lane];
#pragma unroll
        for (int d = 1; d < 32; d <<= 1) {
            int n2 = __shfl_up_sync(FULL, x, d);
            if (lane >= d) x += n2;
        }
        wsum[lane] = x;
    }
    __syncthreads();
    if (own) {
        int run = s - local + ((wid > 0) ? wsum[wid - 1] : 0);  // exclusive
#pragma unroll
        for (int i = 0; i < BPT; i++) {
            int b = base - i;
            run += hist[b];
            hist[b] = run;
        }
    }
    __syncthreads();
}

// Boundary pick on suffix-summed hist: hist[b] >= krem > hist[b+1].
// Writes {b, krem - hist[b+1]}. Ends with __syncthreads.
template<int NB, int BPT>
__device__ __forceinline__ void pick(const int* hist, int krem, int* bcast)
{
    const int tid = threadIdx.x;
    if ((tid * BPT) < NB) {
        const int base = NB - 1 - tid * BPT;
#pragma unroll
        for (int i = 0; i < BPT; i++) {
            int b = base - i;
            int S = hist[b], Sn = hist[b + 1];
            if (S >= krem && Sn < krem) {   // unique (suffix monotone)
                bcast[0] = b;
                bcast[1] = krem - Sn;
            }
        }
    }
    __syncthreads();
}

__global__ void __launch_bounds__(1024)
select_kernel(float* __restrict__ out)
{
    __shared__ int hist[2049];
    __shared__ int wsum[32];
    __shared__ int bcast[2];

    const int b = blockIdx.x, tid = threadIdx.x;
    const int lane = tid & 31, wid = tid >> 5;
    const unsigned int* keys = g_keys + b * SEQ;
    float* o = out + b * SEQ;

    // Contiguous ownership: indices [tid*8, tid*8+8)
    const uint4 k0 = __ldcg(reinterpret_cast<const uint4*>(keys) + tid * 2);
    const uint4 k1 = __ldcg(reinterpret_cast<const uint4*>(keys) + tid * 2 + 1);
    unsigned int v[8] = {k0.x, k0.y, k0.z, k0.w, k1.x, k1.y, k1.z, k1.w};

    // Load prebuilt pass-1 histogram into SMEM; reset gmem copy for replay.
    {
        int* gh = g_hist + b * 2048;
        int h0 = __ldcg(gh + tid);
        int h1 = __ldcg(gh + tid + 1024);
        hist[tid] = h0;
        hist[tid + 1024] = h1;
        gh[tid] = 0;
        gh[tid + 1024] = 0;
        if (tid == 0) hist[2048] = 0;
    }
    __syncthreads();

    // Suffix scan; n_active = suffix at bin 1 (bin 0 holds only inactive keys).
    suffix_scan<2048, 2>(hist, wsum);
    const int n_active = hist[1];

    if (n_active == 0) {
        float4 z = make_float4(0.f, 0.f, 0.f, 0.f);
        reinterpret_cast<float4*>(o)[tid * 2]     = z;
        reinterpret_cast<float4*>(o)[tid * 2 + 1] = z;
        return;
    }
    const int k = (n_active + 1) >> 1;   // max(1, ceil(n/2)), n >= 1

    // ---- Pass 1 boundary (prebuilt): bits [31:21] ----
    pick<2048, 2>(hist, k, bcast);
    unsigned int prefix = ((unsigned int)bcast[0]) << 21;
    int krem = bcast[1];

    // ---- Pass 2: bits [20:10], 2048 bins, prefix-matching keys ----
    hist[tid] = 0; hist[tid + 1024] = 0;     // sentinel hist[2048] still 0
    __syncthreads();
#pragma unroll
    for (int i = 0; i < 8; i++)
        if ((v[i] & 0xFFE00000u) == prefix)
            atomicAdd(&hist[(v[i] >> 10) & 2047u], 1);
    __syncthreads();
    suffix_scan<2048, 2>(hist, wsum);
    pick<2048, 2>(hist, krem, bcast);
    prefix |= ((unsigned int)bcast[0]) << 10;
    krem = bcast[1];

    // ---- Pass 3: bits [9:0], 1024 bins ----
    hist[tid] = 0;
    if (tid == 0) hist[1024] = 0;
    __syncthreads();
#pragma unroll
    for (int i = 0; i < 8; i++)
        if ((v[i] & 0xFFFFFC00u) == prefix)
            atomicAdd(&hist[v[i] & 1023u], 1);
    __syncthreads();
    suffix_scan<1024, 1>(hist, wsum);
    pick<1024, 1>(hist, krem, bcast);
    const unsigned int t = prefix | (unsigned int)bcast[0];
    // Radix-select invariant: residual krem == k - #(keys > t) == mneed.
    const int mneed = bcast[1];

    // ---- stable rank among equals: exclusive block scan (thread order ==
    //      index order thanks to contiguous ownership) ----
    int le = 0;
#pragma unroll
    for (int i = 0; i < 8; i++) le += (v[i] == t);
    int s = le;
#pragma unroll
    for (int d = 1; d < 32; d <<= 1) {
        int n2 = __shfl_up_sync(FULL, s, d);
        if (lane >= d) s += n2;
    }
    if (lane == 31) wsum[wid] = s;
    __syncthreads();
    if (wid == 0) {
        int x = wsum[lane];
#pragma unroll
        for (int d = 1; d < 32; d <<= 1) {
            int n2 = __shfl_up_sync(FULL, x, d);
            if (lane >= d) x += n2;
        }
        wsum[lane] = x;
    }
    __syncthreads();
    int eq_rank = s - le + ((wid > 0) ? wsum[wid - 1] : 0);

    // ---- emit keep mask as float 1.0/0.0 ----
    float r8[8];
#pragma unroll
    for (int i = 0; i < 8; i++) {
        bool keep;
        if (v[i] > t)       keep = true;
        else if (v[i] == t) { keep = (eq_rank < mneed); eq_rank++; }
        else                keep = false;
        r8[i] = keep ? 1.0f : 0.0f;
    }
    reinterpret_cast<float4*>(o)[tid * 2]     = make_float4(r8[0], r8[1], r8[2], r8[3]);
    reinterpret_cast<float4*>(o)[tid * 2 + 1] = make_float4(r8[4], r8[5], r8[6], r8[7]);
}

extern "C" void kernel_launch(void* const* d_in, const int* in_sizes, int n_in,
                              void* d_out, int out_size)
{
    // Bind inputs by element count (all distinct):
    //   hidden 67108864, mask 65536, w 1024, bias 1
    const float*        hidden = nullptr;
    const unsigned int* mask   = nullptr;
    const float*        w      = nullptr;
    const float*        bias   = nullptr;
    for (int i = 0; i < n_in; i++) {
        if      (in_sizes[i] == 67108864) hidden = (const float*)d_in[i];
        else if (in_sizes[i] == 65536)    mask   = (const unsigned int*)d_in[i];
        else if (in_sizes[i] == 1024)     w      = (const float*)d_in[i];
        else if (in_sizes[i] == 1)        bias   = (const float*)d_in[i];
    }
    float* out = (float*)d_out;

    score_kernel<<<NTOK / 8, 256>>>(hidden, mask, w, bias);
    select_kernel<<<BATCH, 1024>>>(out);
}

// round 12
// speedup vs baseline: 1.1388x; 1.1388x over previous
#include <cuda_runtime.h>
#include <cuda_bf16.h>

#define BATCH 8
#define SEQ   8192
#define DMODEL 1024
#define NTOK (BATCH * SEQ)
#define FULL 0xFFFFFFFFu

// Scratch: sortable keys per token. Active key = monotone uint transform of
// score (always >= 0x00800000); inactive = 0.
__device__ unsigned int g_keys[NTOK];

// ---------------------------------------------------------------------------
// Kernel 1: scores[b,s] = dot(hidden[b,s,:], w) + bias ; key = sortable(score)
// One warp per token; streams 256 MB of hidden once (HBM-bound, ~6.2 TB/s).
// EXACTLY the R9 configuration — do not touch.
// ---------------------------------------------------------------------------
__global__ void __launch_bounds__(256)
score_kernel(const float* __restrict__ hidden,
             const unsigned int* __restrict__ mask,
             const float* __restrict__ w,
             const float* __restrict__ bias)
{
    int warp = (blockIdx.x * blockDim.x + threadIdx.x) >> 5;
    int lane = threadIdx.x & 31;
    if (warp >= NTOK) return;

    const float4* hp = reinterpret_cast<const float4*>(hidden + (size_t)warp * DMODEL);
    const float4* wp = reinterpret_cast<const float4*>(w);

    float acc = 0.0f;
#pragma unroll
    for (int i = 0; i < 8; i++) {
        float4 a = __ldcs(hp + lane + i * 32);   // streaming, evict-first
        float4 c = wp[lane + i * 32];            // hot in L1
        acc += a.x * c.x + a.y * c.y + a.z * c.z + a.w * c.w;
    }
#pragma unroll
    for (int o = 16; o; o >>= 1) acc += __shfl_xor_sync(FULL, acc, o);

    if (lane == 0) {
        float s = acc + bias[0];
        unsigned int u = __float_as_uint(s);
        u = (u & 0x80000000u) ? ~u : (u | 0x80000000u);  // order-preserving
        g_keys[warp] = (mask[warp] != 0u) ? u : 0u;      // inactive -> 0
    }
}

// ---------------------------------------------------------------------------
// Kernel 2: per-row exact variable top-k, stable lowest-index tie break.
// One block/row, 1024 threads, 8 contiguous keys/thread in registers.
// Pass 1 [31:21] uses 4-way interleaved sub-histograms (conflict-spread
// ATOMS); passes 2 [20:10] / 3 [9:0] single histogram (few participants).
// n_active and mneed fall out of the scan/radix invariants (no block
// reduces anywhere).
// ---------------------------------------------------------------------------
__global__ void __launch_bounds__(1024)
select_kernel(float* __restrict__ out)
{
    __shared__ int hist[2048 * 4];   // pass1: [bin*4+copy]; passes 2/3: [bin]
    __shared__ int wsum[32];
    __shared__ int bcast[2];

    const int b = blockIdx.x, tid = threadIdx.x;
    const int lane = tid & 31, wid = tid >> 5;
    const unsigned int* keys = g_keys + b * SEQ;
    float* o = out + b * SEQ;

    // Contiguous ownership: indices [tid*8, tid*8+8)
    const uint4 k0 = reinterpret_cast<const uint4*>(keys)[tid * 2];
    const uint4 k1 = reinterpret_cast<const uint4*>(keys)[tid * 2 + 1];
    unsigned int v[8] = {k0.x, k0.y, k0.z, k0.w, k1.x, k1.y, k1.z, k1.w};

    // ---- Pass 1 zero: 8192 ints via 2 STS.128/thread ----
    {
        int4* h4 = reinterpret_cast<int4*>(hist);
        int4 z4 = make_int4(0, 0, 0, 0);
        h4[tid] = z4;
        h4[tid + 1024] = z4;
    }
    __syncthreads();

    // ---- Pass 1 histogram: bits [31:21], 4 interleaved copies ----
    const int copy = wid & 3;
#pragma unroll
    for (int i = 0; i < 8; i++)
        atomicAdd(&hist[(v[i] >> 21) * 4 + copy], 1);
    __syncthreads();

    // ---- Pass 1 merge + suffix scan (BPT=2). Suffix stored at hist[b]. ----
    int n_active, k, krem;
    unsigned int prefix;
    {
        const int base = 2047 - tid * 2;   // owns bins {base, base-1}
        int4 c0 = reinterpret_cast<int4*>(hist)[base];
        int4 c1 = reinterpret_cast<int4*>(hist)[base - 1];
        int h_hi = c0.x + c0.y + c0.z + c0.w;   // count of bin `base`
        int h_lo = c1.x + c1.y + c1.z + c1.w;   // count of bin `base-1`
        int local = h_hi + h_lo;

        int s = local;
#pragma unroll
        for (int d = 1; d < 32; d <<= 1) {
            int n2 = __shfl_up_sync(FULL, s, d);
            if (lane >= d) s += n2;
        }
        if (lane == 31) wsum[wid] = s;
        __syncthreads();
        if (wid == 0) {
            int x = wsum[lane];
#pragma unroll
            for (int d = 1; d < 32; d <<= 1) {
                int n2 = __shfl_up_sync(FULL, x, d);
                if (lane >= d) x += n2;
            }
            wsum[lane] = x;
        }
        __syncthreads();
        int run = s - local + ((wid > 0) ? wsum[wid - 1] : 0);  // exclusive
        hist[base]     = run + h_hi;          // suffix(base)
        hist[base - 1] = run + h_hi + h_lo;   // suffix(base-1)
        if (tid == 0) hist[2048] = 0;         // sentinel
        __syncthreads();

        // n_active = suffix at bin 1 (bin 0 = inactive keys only).
        n_active = hist[1];
        if (n_active == 0) {
            float4 z = make_float4(0.f, 0.f, 0.f, 0.f);
            reinterpret_cast<float4*>(o)[tid * 2]     = z;
            reinterpret_cast<float4*>(o)[tid * 2 + 1] = z;
            return;
        }
        k = (n_active + 1) >> 1;   // max(1, ceil(n/2)), n >= 1

        // Boundary pick: hist[b] >= k > hist[b+1]
#pragma unroll
        for (int i = 0; i < 2; i++) {
            int bb = base - i;
            int S = hist[bb], Sn = hist[bb + 1];
            if (S >= k && Sn < k) { bcast[0] = bb; bcast[1] = k - Sn; }
        }
        __syncthreads();
        prefix = ((unsigned int)bcast[0]) << 21;
        krem = bcast[1];
    }

    // ---- Pass 2: bits [20:10], 2048 bins, prefix-matching keys only ----
    hist[tid] = 0; hist[tid + 1024] = 0;
    if (tid == 0) hist[2048] = 0;
    __syncthreads();
#pragma unroll
    for (int i = 0; i < 8; i++)
        if ((v[i] & 0xFFE00000u) == prefix)
            atomicAdd(&hist[(v[i] >> 10) & 2047u], 1);
    __syncthreads();
    {
        const int base = 2047 - tid * 2;
        int h_hi = hist[base], h_lo = hist[base - 1];
        int local = h_hi + h_lo;
        int s = local;
#pragma unroll
        for (int d = 1; d < 32; d <<= 1) {
            int n2 = __shfl_up_sync(FULL, s, d);
            if (lane >= d) s += n2;
        }
        if (lane == 31) wsum[wid] = s;
        __syncthreads();
        if (wid == 0) {
            int x = wsum[lane];
#pragma unroll
            for (int d = 1; d < 32; d <<= 1) {
                int n2 = __shfl_up_sync(FULL, x, d);
                if (lane >= d) x += n2;
            }
            wsum[lane] = x;
        }
        __syncthreads();
        int run = s - local + ((wid > 0) ? wsum[wid - 1] : 0);
        hist[base]     = run + h_hi;
        hist[base - 1] = run + h_hi + h_lo;
        __syncthreads();
#pragma unroll
        for (int i = 0; i < 2; i++) {
            int bb = base - i;
            int S = hist[bb], Sn = hist[bb + 1];
            if (S >= krem && Sn < krem) { bcast[0] = bb; bcast[1] = krem - Sn; }
        }
        __syncthreads();
        prefix |= ((unsigned int)bcast[0]) << 10;
        krem = bcast[1];
    }

    // ---- Pass 3: bits [9:0], 1024 bins ----
    hist[tid] = 0;
    if (tid == 0) hist[1024] = 0;
    __syncthreads();
#pragma unroll
    for (int i = 0; i < 8; i++)
        if ((v[i] & 0xFFFFFC00u) == prefix)
            atomicAdd(&hist[v[i] & 1023u], 1);
    __syncthreads();
    unsigned int t;
    int mneed;
    {
        const int base = 1023 - tid;       // BPT = 1
        int local = hist[base];
        int s = local;
#pragma unroll
        for (int d = 1; d < 32; d <<= 1) {
            int n2 = __shfl_up_sync(FULL, s, d);
            if (lane >= d) s += n2;
        }
        if (lane == 31) wsum[wid] = s;
        __syncthreads();
        if (wid == 0) {
            int x = wsum[lane];
#pragma unroll
            for (int d = 1; d < 32; d <<= 1) {
                int n2 = __shfl_up_sync(FULL, x, d);
                if (lane >= d) x += n2;
            }
            wsum[lane] = x;
        }
        __syncthreads();
        int run = s - local + ((wid > 0) ? wsum[wid - 1] : 0);
        hist[base] = run + local;
        __syncthreads();
        {
            int S = hist[base], Sn = hist[base + 1];
            if (S >= krem && Sn < krem) { bcast[0] = base; bcast[1] = krem - Sn; }
        }
        __syncthreads();
        t = prefix | (unsigned int)bcast[0];
        // Radix invariant: residual == k - #(keys > t) == number of equals
        // to admit (lowest index first). Validated by R11's rel_err=0.
        mneed = bcast[1];
    }

    // ---- stable rank among equals: exclusive block scan (thread order ==
    //      index order thanks to contiguous ownership) ----
    int le = 0;
#pragma unroll
    for (int i = 0; i < 8; i++) le += (v[i] == t);
    int s = le;
#pragma unroll
    for (int d = 1; d < 32; d <<= 1) {
        int n2 = __shfl_up_sync(FULL, s, d);
        if (lane >= d) s += n2;
    }
    if (lane == 31) wsum[wid] = s;
    __syncthreads();
    if (wid == 0) {
        int x = wsum[lane];
#pragma unroll
        for (int d = 1; d < 32; d <<= 1) {
            int n2 = __shfl_up_sync(FULL, x, d);
            if (lane >= d) x += n2;
        }
        wsum[lane] = x;
    }
    __syncthreads();
    int eq_rank = s - le + ((wid > 0) ? wsum[wid - 1] : 0);

    // ---- emit keep mask as float 1.0/0.0 ----
    float r8[8];
#pragma unroll
    for (int i = 0; i < 8; i++) {
        bool keep;
        if (v[i] > t)       keep = true;
        else if (v[i] == t) { keep = (eq_rank < mneed); eq_rank++; }
        else                keep = false;
        r8[i] = keep ? 1.0f : 0.0f;
    }
    reinterpret_cast<float4*>(o)[tid * 2]     = make_float4(r8[0], r8[1], r8[2], r8[3]);
    reinterpret_cast<float4*>(o)[tid * 2 + 1] = make_float4(r8[4], r8[5], r8[6], r8[7]);
}

extern "C" void kernel_launch(void* const* d_in, const int* in_sizes, int n_in,
                              void* d_out, int out_size)
{
    // Bind inputs by element count (all distinct):
    //   hidden 67108864, mask 65536, w 1024, bias 1
    const float*        hidden = nullptr;
    const unsigned int* mask   = nullptr;
    const float*        w      = nullptr;
    const float*        bias   = nullptr;
    for (int i = 0; i < n_in; i++) {
        if      (in_sizes[i] == 67108864) hidden = (const float*)d_in[i];
        else if (in_sizes[i] == 65536)    mask   = (const unsigned int*)d_in[i];
        else if (in_sizes[i] == 1024)     w      = (const float*)d_in[i];
        else if (in_sizes[i] == 1)        bias   = (const float*)d_in[i];
    }
    float* out = (float*)d_out;

    score_kernel<<<NTOK / 8, 256>>>(hidden, mask, w, bias);
    select_kernel<<<BATCH, 1024>>>(out);
}